// round 16
// baseline (speedup 1.0000x reference)
#include <cuda_runtime.h>
#include <cuda_bf16.h>
#include <cstdint>
#include <stdint.h>
#include <math.h>

typedef __nv_bfloat16 bf16;

// ---------------- problem constants ----------------
#define TOK   2048
#define CDIM  1024
#define HH    16
#define DH    64
#define TT    1024
#define BB    2
#define NHID  4096
#define WIN   256

// ---------------- scratch ----------------
__device__ float g_xn2  [TOK * CDIM];
__device__ float g_m    [TOK];
__device__ float g_coef [TOK];
__device__ int   g_eidx [TOK];
__device__ int   g_perm [TOK];
__device__ int   g_cnt  [2];

__device__ bf16 g_xnh  [TOK * CDIM];
__device__ bf16 g_xn2h [TOK * CDIM];
__device__ bf16 g_qkvh [TOK * 3072];
__device__ bf16 g_krh  [32 * 64 * 1024];
__device__ bf16 g_sch  [32u * 1024u * 1024u];   // bf16 scores
__device__ bf16 g_wh   [32u * 1024u * 1024u];   // bf16 probs
__device__ bf16 g_oh   [TOK * CDIM];
__device__ bf16 g_h1h  [TOK * NHID];
__device__ bf16 g_sxh  [TOK * NHID];
__device__ bf16 g_gluh [TOK * NHID];
__device__ bf16 g_acth [TOK * NHID];
__device__ bf16 g_Wqkvh[CDIM * 3072];
__device__ bf16 g_wph  [CDIM * CDIM];
__device__ bf16 g_w1h  [2 * CDIM * NHID];
__device__ bf16 g_wsh  [2 * NHID * NHID];
__device__ bf16 g_wgh  [2 * NHID * NHID];
__device__ bf16 g_w2h  [2 * NHID * CDIM];

// ================= mma.sync machinery =================
__device__ __forceinline__ void ldsm4(uint32_t r[4], uint32_t addr) {
    asm volatile("ldmatrix.sync.aligned.m8n8.x4.shared.b16 {%0,%1,%2,%3},[%4];"
        : "=r"(r[0]), "=r"(r[1]), "=r"(r[2]), "=r"(r[3]) : "r"(addr));
}
__device__ __forceinline__ void ldsm4t(uint32_t r[4], uint32_t addr) {
    asm volatile("ldmatrix.sync.aligned.m8n8.x4.trans.shared.b16 {%0,%1,%2,%3},[%4];"
        : "=r"(r[0]), "=r"(r[1]), "=r"(r[2]), "=r"(r[3]) : "r"(addr));
}
__device__ __forceinline__ void mma16816(float d[4], const uint32_t a[4], const uint32_t b[2]) {
    asm volatile("mma.sync.aligned.m16n8k16.row.col.f32.bf16.bf16.f32 "
        "{%0,%1,%2,%3},{%4,%5,%6,%7},{%8,%9},{%0,%1,%2,%3};"
        : "+f"(d[0]), "+f"(d[1]), "+f"(d[2]), "+f"(d[3])
        : "r"(a[0]), "r"(a[1]), "r"(a[2]), "r"(a[3]), "r"(b[0]), "r"(b[1]));
}
__device__ __forceinline__ void cp16(uint32_t dst, const void* src) {
    asm volatile("cp.async.cg.shared.global [%0],[%1],16;" :: "r"(dst), "l"(src));
}

// ===== GEMM core (R6-proven): block 128 x BN, BK=32, 2-stage cp.async, 8 warps (4m x 2n) =====
template<int BN>
__device__ __forceinline__ void hgemm_core2(
    const bf16* __restrict__ A, int lda, const int* __restrict__ gather, int row0,
    const bf16* __restrict__ B, int ldb, int K,
    float (&acc)[2][BN/16][4])
{
    const int BPAD = BN + 8;
    const int JP = BN / 32;
    __shared__ __align__(16) bf16 As[2][128][40];
    __shared__ __align__(16) bf16 Bs[2][32][BN + 8];
    const uint32_t ASTG = 128 * 40 * 2;
    const uint32_t BSTG = 32 * (uint32_t)BPAD * 2;

    const int tid = threadIdx.x;
    const int lane = tid & 31, warp = tid >> 5;
    const int wm = (warp >> 1) * 32, wn = (warp & 1) * (BN / 2);

    const int ar = tid >> 2, ac = (tid & 3) * 8;
    int ga0 = gather ? gather[row0 + ar]      : (row0 + ar);
    int ga1 = gather ? gather[row0 + ar + 64] : (row0 + ar + 64);
    const bf16* pa0 = A + (size_t)ga0 * lda + ac;
    const bf16* pa1 = A + (size_t)ga1 * lda + ac;

    int br, bc;
    if (BN == 128) { br = tid >> 4; bc = (tid & 15) * 8; }
    else           { br = tid >> 3; bc = (tid & 7) * 8; }
    const bf16* pb0 = B + (size_t)br * ldb + bc;
    const bf16* pb1 = B + (size_t)(br + 16) * ldb + bc;

    uint32_t as_base = (uint32_t)__cvta_generic_to_shared(&As[0][0][0]);
    uint32_t bs_base = (uint32_t)__cvta_generic_to_shared(&Bs[0][0][0]);

    uint32_t a_dst0 = as_base + (uint32_t)((ar * 40 + ac) * 2);
    uint32_t a_dst1 = as_base + (uint32_t)(((ar + 64) * 40 + ac) * 2);
    uint32_t b_dst0 = bs_base + (uint32_t)((br * BPAD + bc) * 2);
    uint32_t b_dst1 = bs_base + (uint32_t)(((br + 16) * BPAD + bc) * 2);

    uint32_t aaddr[2], baddr[JP];
    #pragma unroll
    for (int f = 0; f < 2; f++)
        aaddr[f] = as_base + (uint32_t)(((wm + f*16 + (lane & 15)) * 40 + (lane >> 4) * 8) * 2);
    #pragma unroll
    for (int jp = 0; jp < JP; jp++)
        baddr[jp] = bs_base + (uint32_t)((((lane & 7) + ((lane >> 3) & 1) * 8) * BPAD
                                          + wn + jp*16 + (lane >> 4) * 8) * 2);

    const int nsteps = K >> 5;
    {
        cp16(a_dst0, pa0);
        cp16(a_dst1, pa1);
        cp16(b_dst0, pb0);
        if (BN == 128) cp16(b_dst1, pb1);
        asm volatile("cp.async.commit_group;");
    }
    for (int it = 0; it < nsteps; it++) {
        uint32_t buf = (uint32_t)(it & 1);
        if (it + 1 < nsteps) {
            int k0 = (it + 1) << 5;
            uint32_t ao = (buf ^ 1) * ASTG, bo = (buf ^ 1) * BSTG;
            cp16(a_dst0 + ao, pa0 + k0);
            cp16(a_dst1 + ao, pa1 + k0);
            cp16(b_dst0 + bo, pb0 + (size_t)k0 * ldb);
            if (BN == 128) cp16(b_dst1 + bo, pb1 + (size_t)k0 * ldb);
            asm volatile("cp.async.commit_group;");
            asm volatile("cp.async.wait_group 1;");
        } else {
            asm volatile("cp.async.wait_group 0;");
        }
        __syncthreads();
        uint32_t aof = buf * ASTG, bof = buf * BSTG;
        #pragma unroll
        for (int ks = 0; ks < 2; ks++) {
            uint32_t a[2][4];
            ldsm4(a[0], aaddr[0] + aof + ks * 32);
            ldsm4(a[1], aaddr[1] + aof + ks * 32);
            #pragma unroll
            for (int jp = 0; jp < JP; jp++) {
                uint32_t b[4];
                ldsm4t(b, baddr[jp] + bof + (uint32_t)(ks * 16 * BPAD * 2));
                mma16816(acc[0][2*jp],   a[0], b);
                mma16816(acc[0][2*jp+1], a[0], b + 2);
                mma16816(acc[1][2*jp],   a[1], b);
                mma16816(acc[1][2*jp+1], a[1], b + 2);
            }
        }
        __syncthreads();
    }
}

// ---------------- weight repack: Wq (summed over q) | Wk | Wv -> bf16 [C x 3072] ----------------
__global__ void k_repack(const float* __restrict__ Wq, const float* __restrict__ Wk,
                         const float* __restrict__ Wv)
{
    int idx = blockIdx.x * blockDim.x + threadIdx.x;
    if (idx >= CDIM * 3072) return;
    int c = idx / 3072, n = idx % 3072;
    float val;
    if (n < 1024) {
        int h = n >> 6, d = n & 63;
        val = Wq[(((size_t)h*2 + 0)*CDIM + c)*DH + d] + Wq[(((size_t)h*2 + 1)*CDIM + c)*DH + d];
    } else if (n < 2048) {
        int m = n - 1024; int h = m >> 6, d = m & 63;
        val = Wk[((size_t)h*CDIM + c)*DH + d];
    } else {
        int m = n - 2048; int h = m >> 6, d = m & 63;
        val = Wv[((size_t)h*CDIM + c)*DH + d];
    }
    g_Wqkvh[idx] = __float2bfloat16(val);
}

// ---------------- fp32 -> bf16 weight conversion (expert weights + Wp) ----------------
__global__ void k_convw(const float* __restrict__ Ew1, const float* __restrict__ Ews,
                        const float* __restrict__ Ewg, const float* __restrict__ Ew2,
                        const float* __restrict__ Wp)
{
    const long long N1 = 2LL * CDIM * NHID;     // 8388608
    const long long NS = 2LL * NHID * NHID;     // 33554432
    const long long NP = (long long)CDIM * CDIM;// 1048576
    long long i = (long long)(blockIdx.x * blockDim.x + threadIdx.x) * 4;
    const float* s; bf16* d; long long off;
    if (i < N1)                    { s = Ew1; d = g_w1h; off = i; }
    else if (i < N1 + NS)          { s = Ews; d = g_wsh; off = i - N1; }
    else if (i < N1 + 2*NS)        { s = Ewg; d = g_wgh; off = i - N1 - NS; }
    else if (i < 2*N1 + 2*NS)      { s = Ew2; d = g_w2h; off = i - N1 - 2*NS; }
    else if (i < 2*N1 + 2*NS + NP) { s = Wp;  d = g_wph; off = i - 2*N1 - 2*NS; }
    else return;
    float4 v = *(const float4*)(s + off);
    __nv_bfloat162* p = (__nv_bfloat162*)(d + off);
    p[0] = __floats2bfloat162_rn(v.x, v.y);
    p[1] = __floats2bfloat162_rn(v.z, v.w);
}

// ---------------- layernorm (ddof=1) ----------------
__global__ void __launch_bounds__(256) k_ln(const float* __restrict__ src,
                                            const float* __restrict__ gam,
                                            const float* __restrict__ bet, int dst)
{
    int row = blockIdx.x;
    const float* x = src + (size_t)row * CDIM;
    int tid = threadIdx.x;
    float s = 0.f, ss = 0.f;
    for (int c = tid; c < CDIM; c += 256) { float v = x[c]; s += v; ss += v*v; }
    __shared__ float r0[256], r1[256];
    r0[tid] = s; r1[tid] = ss; __syncthreads();
    for (int o = 128; o > 0; o >>= 1) {
        if (tid < o) { r0[tid] += r0[tid+o]; r1[tid] += r1[tid+o]; }
        __syncthreads();
    }
    float mean = r0[0] * (1.f / CDIM);
    float var  = (r1[0] - CDIM * mean * mean) * (1.f / (CDIM - 1));
    float rstd = rsqrtf(var + 1e-5f);
    for (int c = tid; c < CDIM; c += 256) {
        float v = (x[c] - mean) * rstd * gam[c] + bet[c];
        if (dst) {
            g_xn2[(size_t)row * CDIM + c] = v;
            g_xn2h[(size_t)row * CDIM + c] = __float2bfloat16(v);
        } else {
            g_xnh[(size_t)row * CDIM + c] = __float2bfloat16(v);
        }
    }
}

// ---------------- qkv projection ----------------
__global__ void __launch_bounds__(256, 3) k_hgemm_qkv()
{
    int bm0 = blockIdx.y * 128, bn0 = blockIdx.x * 128;
    float acc[2][8][4] = {};
    hgemm_core2<128>(g_xnh, CDIM, nullptr, bm0, g_Wqkvh + bn0, 3072, CDIM, acc);
    int lane = threadIdx.x & 31, warp = threadIdx.x >> 5;
    int wm = (warp >> 1) * 32, wn = (warp & 1) * 64;
    int gq = lane >> 2, tig = lane & 3;
    #pragma unroll
    for (int f = 0; f < 2; f++) {
        int r = bm0 + wm + f * 16 + gq;
        #pragma unroll
        for (int j = 0; j < 8; j++) {
            int c = bn0 + wn + j * 8 + tig * 2;
            *(__nv_bfloat162*)&g_qkvh[(size_t)r * 3072 + c] =
                __floats2bfloat162_rn(acc[f][j][0], acc[f][j][1]);
            *(__nv_bfloat162*)&g_qkvh[(size_t)(r + 8) * 3072 + c] =
                __floats2bfloat162_rn(acc[f][j][2], acc[f][j][3]);
        }
    }
}

// ---------------- k reorder (reshape-bug map), vectorized x4 ----------------
__global__ void k_krep()
{
    int idx = (blockIdx.x * blockDim.x + threadIdx.x) * 4;   // over 32*64*1024
    int z = idx >> 16, rem = idx & 65535;
    int d = rem >> 10, s = rem & 1023;
    int h = z >> 1, b = z & 1;
    const bf16* src = &g_qkvh[(size_t)(b * TT + 16 * d + (s >> 6)) * 3072 + 1024 + h * 64 + (s & 63)];
    *(uint2*)&g_krh[idx] = *(const uint2*)src;
}

// ---------------- scores = q @ kr * 0.125 -> bf16 (fully-masked tiles skipped) ----------------
__global__ void __launch_bounds__(256, 3) k_hgemm_scores()
{
    int bn0 = blockIdx.x * 128, t0 = blockIdx.y * 128, z = blockIdx.z;
    if (bn0 + 383 <= t0) return;
    int h = z >> 1, b = z & 1;
    const bf16* A = g_qkvh + (size_t)b * TT * 3072 + h * 64;
    const bf16* B = g_krh + (size_t)z * 65536 + bn0;
    float acc[2][8][4] = {};
    hgemm_core2<128>(A, 3072, nullptr, t0, B, 1024, 64, acc);
    int lane = threadIdx.x & 31, warp = threadIdx.x >> 5;
    int wm = (warp >> 1) * 32, wn = (warp & 1) * 64;
    int gq = lane >> 2, tig = lane & 3;
    #pragma unroll
    for (int f = 0; f < 2; f++) {
        int r = t0 + wm + f * 16 + gq;
        #pragma unroll
        for (int j = 0; j < 8; j++) {
            int c = bn0 + wn + j * 8 + tig * 2;
            *(__nv_bfloat162*)&g_sch[(size_t)(z * TT + r) * TT + c] =
                __floats2bfloat162_rn(acc[f][j][0] * 0.125f, acc[f][j][1] * 0.125f);
            *(__nv_bfloat162*)&g_sch[(size_t)(z * TT + r + 8) * TT + c] =
                __floats2bfloat162_rn(acc[f][j][2] * 0.125f, acc[f][j][3] * 0.125f);
        }
    }
}

// ---------------- softmax (bf16 in/out, fp32 stats), contiguous x4 per thread ----------------
__global__ void __launch_bounds__(256) k_softmax()
{
    int t = blockIdx.x, z = blockIdx.y;
    const bf16* row = g_sch + (size_t)(z * TT + t) * TT;
    bf16* rout = g_wh + (size_t)(z * TT + t) * TT;
    int bound = t - (WIN - 1); if (bound < 0) bound = 0;
    int tid = threadIdx.x;
    int base = tid * 4;
    uint2 raw = *(const uint2*)&row[base];
    __nv_bfloat162 p0 = *(__nv_bfloat162*)&raw.x;
    __nv_bfloat162 p1 = *(__nv_bfloat162*)&raw.y;
    float v[4] = { __bfloat162float(p0.x), __bfloat162float(p0.y),
                   __bfloat162float(p1.x), __bfloat162float(p1.y) };
    float mx = -1e30f;
    #pragma unroll
    for (int i = 0; i < 4; i++) {
        if (base + i < bound) v[i] = -1e30f;
        mx = fmaxf(mx, v[i]);
    }
    __shared__ float red[256];
    red[tid] = mx; __syncthreads();
    for (int o = 128; o > 0; o >>= 1) { if (tid < o) red[tid] = fmaxf(red[tid], red[tid+o]); __syncthreads(); }
    mx = red[0]; __syncthreads();
    float sum = 0.f;
    #pragma unroll
    for (int i = 0; i < 4; i++) {
        v[i] = (base + i >= bound) ? expf(v[i] - mx) : 0.f;
        sum += v[i];
    }
    red[tid] = sum; __syncthreads();
    for (int o = 128; o > 0; o >>= 1) { if (tid < o) red[tid] += red[tid+o]; __syncthreads(); }
    float inv = 1.f / red[0];
    __nv_bfloat162 q0 = __floats2bfloat162_rn(v[0] * inv, v[1] * inv);
    __nv_bfloat162 q1 = __floats2bfloat162_rn(v[2] * inv, v[3] * inv);
    uint2 outw; outw.x = *(uint32_t*)&q0; outw.y = *(uint32_t*)&q1;
    *(uint2*)&rout[base] = outw;
}

// ---------------- o = w @ v (leading all-zero K range skipped; bitwise identical) ----------------
__global__ void __launch_bounds__(256, 3) k_hgemm_o()
{
    int t0 = blockIdx.y * 128, z = blockIdx.z;
    int h = z >> 1, b = z & 1;
    int kstart = t0 - 255; if (kstart < 0) kstart = 0;
    kstart &= ~31;
    const bf16* A = g_wh + (size_t)z * TT * TT + kstart;
    const bf16* B = g_qkvh + (size_t)(b * TT + kstart) * 3072 + 2048 + h * 64;
    float acc[2][4][4] = {};
    hgemm_core2<64>(A, TT, nullptr, t0, B, 3072, TT - kstart, acc);
    int lane = threadIdx.x & 31, warp = threadIdx.x >> 5;
    int wm = (warp >> 1) * 32, wn = (warp & 1) * 32;
    int gq = lane >> 2, tig = lane & 3;
    #pragma unroll
    for (int f = 0; f < 2; f++) {
        int r = b * TT + t0 + wm + f * 16 + gq;
        #pragma unroll
        for (int j = 0; j < 4; j++) {
            int c = h * 64 + wn + j * 8 + tig * 2;
            *(__nv_bfloat162*)&g_oh[(size_t)r * CDIM + c] =
                __floats2bfloat162_rn(acc[f][j][0], acc[f][j][1]);
            *(__nv_bfloat162*)&g_oh[(size_t)(r + 8) * CDIM + c] =
                __floats2bfloat162_rn(acc[f][j][2], acc[f][j][3]);
        }
    }
}

// ---------------- x1 = x + o @ Wp + bp -> d_out ----------------
__global__ void __launch_bounds__(256, 3) k_hgemm_wp(const float* __restrict__ x,
                                                     const float* __restrict__ bp,
                                                     float* __restrict__ dout)
{
    int bm0 = blockIdx.y * 128, bn0 = blockIdx.x * 128;
    float acc[2][8][4] = {};
    hgemm_core2<128>(g_oh, CDIM, nullptr, bm0, g_wph + bn0, CDIM, CDIM, acc);
    int lane = threadIdx.x & 31, warp = threadIdx.x >> 5;
    int wm = (warp >> 1) * 32, wn = (warp & 1) * 64;
    int gq = lane >> 2, tig = lane & 3;
    #pragma unroll
    for (int f = 0; f < 2; f++) {
        int r = bm0 + wm + f * 16 + gq;
        #pragma unroll
        for (int j = 0; j < 8; j++) {
            int c = bn0 + wn + j * 8 + tig * 2;
            size_t o0 = (size_t)r * CDIM + c;
            size_t o1 = (size_t)(r + 8) * CDIM + c;
            dout[o0]     = x[o0]     + acc[f][j][0] + bp[c];
            dout[o0 + 1] = x[o0 + 1] + acc[f][j][1] + bp[c + 1];
            dout[o1]     = x[o1]     + acc[f][j][2] + bp[c];
            dout[o1 + 1] = x[o1 + 1] + acc[f][j][3] + bp[c + 1];
        }
    }
}

// ---------------- router / coef / assign ----------------
__global__ void __launch_bounds__(256) k_router(const float* __restrict__ Wg,
                                                const float* __restrict__ bg)
{
    int t = blockIdx.x;
    const float* xr = g_xn2 + (size_t)t * CDIM;
    int tid = threadIdx.x;
    float l0 = 0.f, l1 = 0.f;
    for (int c = tid; c < CDIM; c += 256) {
        float xv = xr[c];
        l0 += xv * Wg[c * 2 + 0];
        l1 += xv * Wg[c * 2 + 1];
    }
    __shared__ float r0[256], r1[256];
    r0[tid] = l0; r1[tid] = l1; __syncthreads();
    for (int o = 128; o > 0; o >>= 1) {
        if (tid < o) { r0[tid] += r0[tid+o]; r1[tid] += r1[tid+o]; }
        __syncthreads();
    }
    if (tid == 0) {
        float a = r0[0] + bg[0], b = r1[0] + bg[1];
        int e = (a >= b) ? 0 : 1;
        g_eidx[t] = e;
        g_m[t] = fmaxf(a, b);
    }
}

// coef softmax over token dim per batch; also zeroes g_cnt
__global__ void __launch_bounds__(256) k_coef()
{
    int b = blockIdx.x, tid = threadIdx.x;
    if (tid == 0) g_cnt[b] = 0;
    __shared__ float red[256];
    float v[4]; float mx = -1e30f;
    #pragma unroll
    for (int i = 0; i < 4; i++) { v[i] = g_m[b * TT + tid + i*256]; mx = fmaxf(mx, v[i]); }
    red[tid] = mx; __syncthreads();
    for (int o = 128; o > 0; o >>= 1) { if (tid < o) red[tid] = fmaxf(red[tid], red[tid+o]); __syncthreads(); }
    mx = red[0]; __syncthreads();
    float sum = 0.f;
    #pragma unroll
    for (int i = 0; i < 4; i++) { v[i] = expf(v[i] - mx); sum += v[i]; }
    red[tid] = sum; __syncthreads();
    for (int o = 128; o > 0; o >>= 1) { if (tid < o) red[tid] += red[tid+o]; __syncthreads(); }
    float inv = 1.f / red[0];
    #pragma unroll
    for (int i = 0; i < 4; i++) g_coef[b * TT + tid + i*256] = v[i] * inv;
}

__global__ void k_assign()
{
    int t = blockIdx.x * blockDim.x + threadIdx.x;
    if (t >= TOK) return;
    int e = g_eidx[t];
    int pos = atomicAdd(&g_cnt[e], 1);
    int row = (e == 0) ? pos : (TOK - 1 - pos);
    g_perm[row] = t;
}

// ================= MoE GEMMs (bf16 weights) =================
__global__ void __launch_bounds__(256, 3) k_hgemm_h1(const float* __restrict__ Eb1)
{
    int e = blockIdx.z, bm0 = blockIdx.y * 128, bn0 = blockIdx.x * 128;
    int cnt0 = g_cnt[0];
    if (e == 0 && bm0 >= cnt0) return;
    if (e == 1 && bm0 + 128 <= cnt0) return;
    float acc[2][8][4] = {};
    hgemm_core2<128>(g_xn2h, CDIM, g_perm, bm0, g_w1h + (size_t)e * CDIM * NHID + bn0, NHID, CDIM, acc);

    int lane = threadIdx.x & 31, warp = threadIdx.x >> 5;
    int wm = (warp >> 1) * 32, wn = (warp & 1) * 64;
    int gq = lane >> 2, tig = lane & 3;
    const float* bias = Eb1 + (size_t)e * NHID;
    #pragma unroll
    for (int f = 0; f < 2; f++) {
        int r = bm0 + wm + f * 16 + gq;
        bool v0 = (e == 0) ? (r < cnt0)     : (r >= cnt0);
        bool v1 = (e == 0) ? (r + 8 < cnt0) : (r + 8 >= cnt0);
        #pragma unroll
        for (int j = 0; j < 8; j++) {
            int c = bn0 + wn + j * 8 + tig * 2;
            float b0 = bias[c], b1 = bias[c + 1];
            if (v0) *(__nv_bfloat162*)&g_h1h[(size_t)r * NHID + c] =
                __floats2bfloat162_rn(acc[f][j][0] + b0, acc[f][j][1] + b1);
            if (v1) *(__nv_bfloat162*)&g_h1h[(size_t)(r + 8) * NHID + c] =
                __floats2bfloat162_rn(acc[f][j][2] + b0, acc[f][j][3] + b1);
        }
    }
}

// merged ff pair: z = e*2 + which; writes bf16 sx/glu
__global__ void __launch_bounds__(256, 3) k_hgemm_ff(const float* __restrict__ Ebs,
                                                     const float* __restrict__ Ebg)
{
    int z = blockIdx.z;
    int e = z >> 1, which = z & 1;
    int bm0 = blockIdx.y * 128, bn0 = blockIdx.x * 128;
    int cnt0 = g_cnt[0];
    if (e == 0 && bm0 >= cnt0) return;
    if (e == 1 && bm0 + 128 <= cnt0) return;
    const bf16* W = (which ? g_wgh : g_wsh) + (size_t)e * NHID * NHID + bn0;
    const float* bias_all = which ? Ebg : Ebs;
    bf16* out = which ? g_gluh : g_sxh;
    float acc[2][8][4] = {};
    hgemm_core2<128>(g_h1h, NHID, nullptr, bm0, W, NHID, NHID, acc);

    int lane = threadIdx.x & 31, warp = threadIdx.x >> 5;
    int wm = (warp >> 1) * 32, wn = (warp & 1) * 64;
    int gq = lane >> 2, tig = lane & 3;
    const float* bias = bias_all + (size_t)e * NHID;
    #pragma unroll
    for (int f = 0; f < 2; f++) {
        int r = bm0 + wm + f * 16 + gq;
        bool v0 = (e == 0) ? (r < cnt0)     : (r >= cnt0);
        bool v1 = (e == 0) ? (r + 8 < cnt0) : (r + 8 >= cnt0);
        #pragma unroll
        for (int j = 0; j < 8; j++) {
            int c = bn0 + wn + j * 8 + tig * 2;
            float b0 = bias[c], b1 = bias[c + 1];
            if (v0) *(__nv_bfloat162*)&out[(size_t)r * NHID + c] =
                __floats2bfloat162_rn(acc[f][j][0] + b0, acc[f][j][1] + b1);
            if (v1) *(__nv_bfloat162*)&out[(size_t)(r + 8) * NHID + c] =
                __floats2bfloat162_rn(acc[f][j][2] + b0, acc[f][j][3] + b1);
        }
    }
}

// act = (sx * sigmoid(beta*sx)) * glu, bf16 in -> bf16 out, x4 vectorized
__global__ void k_act(const float* __restrict__ Ebeta)
{
    size_t i4 = (size_t)(blockIdx.x * blockDim.x + threadIdx.x) * 4;
    if (i4 >= (size_t)TOK * NHID) return;
    int row = (int)(i4 >> 12);
    int e = (row < g_cnt[0]) ? 0 : 1;
    float beta = Ebeta[e];
    uint2 sv = *(const uint2*)&g_sxh[i4];
    uint2 gv = *(const uint2*)&g_gluh[i4];
    __nv_bfloat162 s0 = *(__nv_bfloat162*)&sv.x, s1 = *(__nv_bfloat162*)&sv.y;
    __nv_bfloat162 g0 = *(__nv_bfloat162*)&gv.x, g1 = *(__nv_bfloat162*)&gv.y;
    float s[4] = { __bfloat162float(s0.x), __bfloat162float(s0.y),
                   __bfloat162float(s1.x), __bfloat162float(s1.y) };
    float g[4] = { __bfloat162float(g0.x), __bfloat162float(g0.y),
                   __bfloat162float(g1.x), __bfloat162float(g1.y) };
    float o[4];
    #pragma unroll
    for (int i = 0; i < 4; i++)
        o[i] = s[i] * (1.f / (1.f + expf(-beta * s[i]))) * g[i];
    __nv_bfloat162 q0 = __floats2bfloat162_rn(o[0], o[1]);
    __nv_bfloat162 q1 = __floats2bfloat162_rn(o[2], o[3]);
    uint2 outw; outw.x = *(uint32_t*)&q0; outw.y = *(uint32_t*)&q1;
    *(uint2*)&g_acth[i4] = outw;
}

__global__ void __launch_bounds__(256, 3) k_hgemm_out(const float* __restrict__ Eb2,
                                                      float* __restrict__ dout)
{
    int e = blockIdx.z, bm0 = blockIdx.y * 128, bn0 = blockIdx.x * 128;
    int cnt0 = g_cnt[0];
    if (e == 0 && bm0 >= cnt0) return;
    if (e == 1 && bm0 + 128 <= cnt0) return;
    float acc[2][8][4] = {};
    hgemm_core2<128>(g_acth, NHID, nullptr, bm0, g_w2h + (size_t)e * NHID * CDIM + bn0, CDIM, NHID, acc);

    int lane = threadIdx.x & 31, warp = threadIdx.x >> 5;
    int wm = (warp >> 1) * 32, wn = (warp & 1) * 64;
    int gq = lane >> 2, tig = lane & 3;
    const float* bias = Eb2 + (size_t)e * CDIM;
    #pragma unroll
    for (int f = 0; f < 2; f++) {
        int r = bm0 + wm + f * 16 + gq;
        bool v0 = (e == 0) ? (r < cnt0)     : (r >= cnt0);
        bool v1 = (e == 0) ? (r + 8 < cnt0) : (r + 8 >= cnt0);
        int tok0 = v0 ? g_perm[r]     : 0;
        int tok1 = v1 ? g_perm[r + 8] : 0;
        float cf0 = v0 ? g_coef[tok0] : 0.f;
        float cf1 = v1 ? g_coef[tok1] : 0.f;
        #pragma unroll
        for (int j = 0; j < 8; j++) {
            int c = bn0 + wn + j * 8 + tig * 2;
            float b0 = bias[c], b1 = bias[c + 1];
            if (v0) {
                size_t o = (size_t)tok0 * CDIM + c;
                dout[o]     += cf0 * (acc[f][j][0] + b0);
                dout[o + 1] += cf0 * (acc[f][j][1] + b1);
            }
            if (v1) {
                size_t o = (size_t)tok1 * CDIM + c;
                dout[o]     += cf1 * (acc[f][j][2] + b0);
                dout[o + 1] += cf1 * (acc[f][j][3] + b1);
            }
        }
    }
}

// ---------------- launch ----------------
extern "C" void kernel_launch(void* const* d_in, const int* in_sizes, int n_in,
                              void* d_out, int out_size)
{
    const float* x     = (const float*)d_in[0];
    const float* Wq    = (const float*)d_in[1];
    const float* Wk    = (const float*)d_in[2];
    const float* Wv    = (const float*)d_in[3];
    const float* Wp    = (const float*)d_in[4];
    const float* bp    = (const float*)d_in[5];
    const float* ln1g  = (const float*)d_in[6];
    const float* ln1b  = (const float*)d_in[7];
    const float* ln2g  = (const float*)d_in[8];
    const float* ln2b  = (const float*)d_in[9];
    const float* Wg    = (const float*)d_in[10];
    const float* bg    = (const float*)d_in[11];
    const float* Ew1   = (const float*)d_in[12];
    const float* Eb1   = (const float*)d_in[13];
    const float* Ews   = (const float*)d_in[14];
    const float* Ebs   = (const float*)d_in[15];
    const float* Ebeta = (const float*)d_in[16];
    const float* Ewg   = (const float*)d_in[17];
    const float* Ebg   = (const float*)d_in[18];
    const float* Ew2   = (const float*)d_in[19];
    const float* Eb2   = (const float*)d_in[20];
    float* dout = (float*)d_out;

    // weight conversions (serial, R12/R14-proven placement)
    k_convw<<<82944, 256>>>(Ew1, Ews, Ewg, Ew2, Wp);
    k_repack<<<(CDIM * 3072 + 255) / 256, 256>>>(Wq, Wk, Wv);

    // attention (mma.sync bf16)
    k_ln<<<TOK, 256>>>(x, ln1g, ln1b, 0);
    k_hgemm_qkv<<<dim3(24, 16), 256>>>();
    k_krep<<<2048, 256>>>();
    k_hgemm_scores<<<dim3(8, 8, 32), 256>>>();
    k_softmax<<<dim3(1024, 32), 256>>>();
    k_hgemm_o<<<dim3(1, 8, 32), 256>>>();
    k_hgemm_wp<<<dim3(8, 16), 256>>>(x, bp, dout);

    // MoE routing
    k_ln<<<TOK, 256>>>(dout, ln2g, ln2b, 1);
    k_router<<<TOK, 256>>>(Wg, bg);
    k_coef<<<2, 256>>>();
    k_assign<<<8, 256>>>();

    // MoE expert GEMMs (bf16 tensor cores)
    k_hgemm_h1<<<dim3(32, 16, 2), 256>>>(Eb1);
    k_hgemm_ff<<<dim3(32, 16, 4), 256>>>(Ebs, Ebg);
    k_act<<<(TOK * NHID / 4 + 255) / 256, 256>>>(Ebeta);
    k_hgemm_out<<<dim3(8, 16, 2), 256>>>(Eb2, dout);
}

// round 17
// speedup vs baseline: 2.2765x; 2.2765x over previous
#include <cuda_runtime.h>
#include <cuda_bf16.h>
#include <cstdint>
#include <stdint.h>
#include <math.h>

typedef __nv_bfloat16 bf16;

// ---------------- problem constants ----------------
#define TOK   2048
#define CDIM  1024
#define HH    16
#define DH    64
#define TT    1024
#define BB    2
#define NHID  4096
#define WIN   256

// ---------------- scratch ----------------
__device__ float g_xn2  [TOK * CDIM];
__device__ float g_m    [TOK];
__device__ float g_coef [TOK];
__device__ int   g_eidx [TOK];
__device__ int   g_perm [TOK];
__device__ int   g_cnt  [2];

__device__ bf16 g_xnh  [TOK * CDIM];
__device__ bf16 g_xn2h [TOK * CDIM];
__device__ bf16 g_qkvh [TOK * 3072];
__device__ bf16 g_krh  [32 * 64 * 1024];
__device__ bf16 g_sch  [32u * 1024u * 1024u];   // bf16 scores
__device__ bf16 g_wh   [32u * 1024u * 1024u];   // bf16 probs
__device__ bf16 g_oh   [TOK * CDIM];
__device__ bf16 g_h1h  [TOK * NHID];
__device__ bf16 g_sxh  [TOK * NHID];
__device__ bf16 g_gluh [TOK * NHID];
__device__ bf16 g_acth [TOK * NHID];
__device__ bf16 g_Wqkvh[CDIM * 3072];
__device__ bf16 g_wph  [CDIM * CDIM];
__device__ bf16 g_w1h  [2 * CDIM * NHID];
__device__ bf16 g_wsh  [2 * NHID * NHID];
__device__ bf16 g_wgh  [2 * NHID * NHID];
__device__ bf16 g_w2h  [2 * NHID * CDIM];

// ================= mma.sync machinery =================
__device__ __forceinline__ void ldsm4(uint32_t r[4], uint32_t addr) {
    asm volatile("ldmatrix.sync.aligned.m8n8.x4.shared.b16 {%0,%1,%2,%3},[%4];"
        : "=r"(r[0]), "=r"(r[1]), "=r"(r[2]), "=r"(r[3]) : "r"(addr));
}
__device__ __forceinline__ void ldsm4t(uint32_t r[4], uint32_t addr) {
    asm volatile("ldmatrix.sync.aligned.m8n8.x4.trans.shared.b16 {%0,%1,%2,%3},[%4];"
        : "=r"(r[0]), "=r"(r[1]), "=r"(r[2]), "=r"(r[3]) : "r"(addr));
}
__device__ __forceinline__ void mma16816(float d[4], const uint32_t a[4], const uint32_t b[2]) {
    asm volatile("mma.sync.aligned.m16n8k16.row.col.f32.bf16.bf16.f32 "
        "{%0,%1,%2,%3},{%4,%5,%6,%7},{%8,%9},{%0,%1,%2,%3};"
        : "+f"(d[0]), "+f"(d[1]), "+f"(d[2]), "+f"(d[3])
        : "r"(a[0]), "r"(a[1]), "r"(a[2]), "r"(a[3]), "r"(b[0]), "r"(b[1]));
}
__device__ __forceinline__ void cp16(uint32_t dst, const void* src) {
    asm volatile("cp.async.cg.shared.global [%0],[%1],16;" :: "r"(dst), "l"(src));
}

// ===== GEMM core (R6-proven): block 128 x BN, BK=32, 2-stage cp.async, 8 warps (4m x 2n) =====
template<int BN>
__device__ __forceinline__ void hgemm_core2(
    const bf16* __restrict__ A, int lda, const int* __restrict__ gather, int row0,
    const bf16* __restrict__ B, int ldb, int K,
    float (&acc)[2][BN/16][4])
{
    const int BPAD = BN + 8;
    const int JP = BN / 32;
    __shared__ __align__(16) bf16 As[2][128][40];
    __shared__ __align__(16) bf16 Bs[2][32][BN + 8];
    const uint32_t ASTG = 128 * 40 * 2;
    const uint32_t BSTG = 32 * (uint32_t)BPAD * 2;

    const int tid = threadIdx.x;
    const int lane = tid & 31, warp = tid >> 5;
    const int wm = (warp >> 1) * 32, wn = (warp & 1) * (BN / 2);

    const int ar = tid >> 2, ac = (tid & 3) * 8;
    int ga0 = gather ? gather[row0 + ar]      : (row0 + ar);
    int ga1 = gather ? gather[row0 + ar + 64] : (row0 + ar + 64);
    const bf16* pa0 = A + (size_t)ga0 * lda + ac;
    const bf16* pa1 = A + (size_t)ga1 * lda + ac;

    int br, bc;
    if (BN == 128) { br = tid >> 4; bc = (tid & 15) * 8; }
    else           { br = tid >> 3; bc = (tid & 7) * 8; }
    const bf16* pb0 = B + (size_t)br * ldb + bc;
    const bf16* pb1 = B + (size_t)(br + 16) * ldb + bc;

    uint32_t as_base = (uint32_t)__cvta_generic_to_shared(&As[0][0][0]);
    uint32_t bs_base = (uint32_t)__cvta_generic_to_shared(&Bs[0][0][0]);

    uint32_t a_dst0 = as_base + (uint32_t)((ar * 40 + ac) * 2);
    uint32_t a_dst1 = as_base + (uint32_t)(((ar + 64) * 40 + ac) * 2);
    uint32_t b_dst0 = bs_base + (uint32_t)((br * BPAD + bc) * 2);
    uint32_t b_dst1 = bs_base + (uint32_t)(((br + 16) * BPAD + bc) * 2);

    uint32_t aaddr[2], baddr[JP];
    #pragma unroll
    for (int f = 0; f < 2; f++)
        aaddr[f] = as_base + (uint32_t)(((wm + f*16 + (lane & 15)) * 40 + (lane >> 4) * 8) * 2);
    #pragma unroll
    for (int jp = 0; jp < JP; jp++)
        baddr[jp] = bs_base + (uint32_t)((((lane & 7) + ((lane >> 3) & 1) * 8) * BPAD
                                          + wn + jp*16 + (lane >> 4) * 8) * 2);

    const int nsteps = K >> 5;
    {
        cp16(a_dst0, pa0);
        cp16(a_dst1, pa1);
        cp16(b_dst0, pb0);
        if (BN == 128) cp16(b_dst1, pb1);
        asm volatile("cp.async.commit_group;");
    }
    for (int it = 0; it < nsteps; it++) {
        uint32_t buf = (uint32_t)(it & 1);
        if (it + 1 < nsteps) {
            int k0 = (it + 1) << 5;
            uint32_t ao = (buf ^ 1) * ASTG, bo = (buf ^ 1) * BSTG;
            cp16(a_dst0 + ao, pa0 + k0);
            cp16(a_dst1 + ao, pa1 + k0);
            cp16(b_dst0 + bo, pb0 + (size_t)k0 * ldb);
            if (BN == 128) cp16(b_dst1 + bo, pb1 + (size_t)k0 * ldb);
            asm volatile("cp.async.commit_group;");
            asm volatile("cp.async.wait_group 1;");
        } else {
            asm volatile("cp.async.wait_group 0;");
        }
        __syncthreads();
        uint32_t aof = buf * ASTG, bof = buf * BSTG;
        #pragma unroll
        for (int ks = 0; ks < 2; ks++) {
            uint32_t a[2][4];
            ldsm4(a[0], aaddr[0] + aof + ks * 32);
            ldsm4(a[1], aaddr[1] + aof + ks * 32);
            #pragma unroll
            for (int jp = 0; jp < JP; jp++) {
                uint32_t b[4];
                ldsm4t(b, baddr[jp] + bof + (uint32_t)(ks * 16 * BPAD * 2));
                mma16816(acc[0][2*jp],   a[0], b);
                mma16816(acc[0][2*jp+1], a[0], b + 2);
                mma16816(acc[1][2*jp],   a[1], b);
                mma16816(acc[1][2*jp+1], a[1], b + 2);
            }
        }
        __syncthreads();
    }
}

// ---------------- weight repack: Wq (summed over q) | Wk | Wv -> bf16 [C x 3072] ----------------
__global__ void k_repack(const float* __restrict__ Wq, const float* __restrict__ Wk,
                         const float* __restrict__ Wv)
{
    int idx = blockIdx.x * blockDim.x + threadIdx.x;
    if (idx >= CDIM * 3072) return;
    int c = idx / 3072, n = idx % 3072;
    float val;
    if (n < 1024) {
        int h = n >> 6, d = n & 63;
        val = Wq[(((size_t)h*2 + 0)*CDIM + c)*DH + d] + Wq[(((size_t)h*2 + 1)*CDIM + c)*DH + d];
    } else if (n < 2048) {
        int m = n - 1024; int h = m >> 6, d = m & 63;
        val = Wk[((size_t)h*CDIM + c)*DH + d];
    } else {
        int m = n - 2048; int h = m >> 6, d = m & 63;
        val = Wv[((size_t)h*CDIM + c)*DH + d];
    }
    g_Wqkvh[idx] = __float2bfloat16(val);
}

// ---------------- fp32 -> bf16 weight conversion (expert weights + Wp) ----------------
__global__ void k_convw(const float* __restrict__ Ew1, const float* __restrict__ Ews,
                        const float* __restrict__ Ewg, const float* __restrict__ Ew2,
                        const float* __restrict__ Wp)
{
    const long long N1 = 2LL * CDIM * NHID;     // 8388608
    const long long NS = 2LL * NHID * NHID;     // 33554432
    const long long NP = (long long)CDIM * CDIM;// 1048576
    long long i = (long long)(blockIdx.x * blockDim.x + threadIdx.x) * 4;
    const float* s; bf16* d; long long off;
    if (i < N1)                    { s = Ew1; d = g_w1h; off = i; }
    else if (i < N1 + NS)          { s = Ews; d = g_wsh; off = i - N1; }
    else if (i < N1 + 2*NS)        { s = Ewg; d = g_wgh; off = i - N1 - NS; }
    else if (i < 2*N1 + 2*NS)      { s = Ew2; d = g_w2h; off = i - N1 - 2*NS; }
    else if (i < 2*N1 + 2*NS + NP) { s = Wp;  d = g_wph; off = i - 2*N1 - 2*NS; }
    else return;
    float4 v = *(const float4*)(s + off);
    __nv_bfloat162* p = (__nv_bfloat162*)(d + off);
    p[0] = __floats2bfloat162_rn(v.x, v.y);
    p[1] = __floats2bfloat162_rn(v.z, v.w);
}

// ---------------- layernorm (ddof=1) ----------------
__global__ void __launch_bounds__(256) k_ln(const float* __restrict__ src,
                                            const float* __restrict__ gam,
                                            const float* __restrict__ bet, int dst)
{
    int row = blockIdx.x;
    const float* x = src + (size_t)row * CDIM;
    int tid = threadIdx.x;
    float s = 0.f, ss = 0.f;
    for (int c = tid; c < CDIM; c += 256) { float v = x[c]; s += v; ss += v*v; }
    __shared__ float r0[256], r1[256];
    r0[tid] = s; r1[tid] = ss; __syncthreads();
    for (int o = 128; o > 0; o >>= 1) {
        if (tid < o) { r0[tid] += r0[tid+o]; r1[tid] += r1[tid+o]; }
        __syncthreads();
    }
    float mean = r0[0] * (1.f / CDIM);
    float var  = (r1[0] - CDIM * mean * mean) * (1.f / (CDIM - 1));
    float rstd = rsqrtf(var + 1e-5f);
    for (int c = tid; c < CDIM; c += 256) {
        float v = (x[c] - mean) * rstd * gam[c] + bet[c];
        if (dst) {
            g_xn2[(size_t)row * CDIM + c] = v;
            g_xn2h[(size_t)row * CDIM + c] = __float2bfloat16(v);
        } else {
            g_xnh[(size_t)row * CDIM + c] = __float2bfloat16(v);
        }
    }
}

// ---------------- qkv projection ----------------
__global__ void __launch_bounds__(256) k_hgemm_qkv()
{
    int bm0 = blockIdx.y * 128, bn0 = blockIdx.x * 128;
    float acc[2][8][4] = {};
    hgemm_core2<128>(g_xnh, CDIM, nullptr, bm0, g_Wqkvh + bn0, 3072, CDIM, acc);
    int lane = threadIdx.x & 31, warp = threadIdx.x >> 5;
    int wm = (warp >> 1) * 32, wn = (warp & 1) * 64;
    int gq = lane >> 2, tig = lane & 3;
    #pragma unroll
    for (int f = 0; f < 2; f++) {
        int r = bm0 + wm + f * 16 + gq;
        #pragma unroll
        for (int j = 0; j < 8; j++) {
            int c = bn0 + wn + j * 8 + tig * 2;
            *(__nv_bfloat162*)&g_qkvh[(size_t)r * 3072 + c] =
                __floats2bfloat162_rn(acc[f][j][0], acc[f][j][1]);
            *(__nv_bfloat162*)&g_qkvh[(size_t)(r + 8) * 3072 + c] =
                __floats2bfloat162_rn(acc[f][j][2], acc[f][j][3]);
        }
    }
}

// ---------------- k reorder (reshape-bug map), vectorized x4 ----------------
__global__ void k_krep()
{
    int idx = (blockIdx.x * blockDim.x + threadIdx.x) * 4;   // over 32*64*1024
    int z = idx >> 16, rem = idx & 65535;
    int d = rem >> 10, s = rem & 1023;
    int h = z >> 1, b = z & 1;
    const bf16* src = &g_qkvh[(size_t)(b * TT + 16 * d + (s >> 6)) * 3072 + 1024 + h * 64 + (s & 63)];
    *(uint2*)&g_krh[idx] = *(const uint2*)src;
}

// ---------------- scores = q @ kr * 0.125 -> bf16 (fully-masked tiles skipped) ----------------
__global__ void __launch_bounds__(256) k_hgemm_scores()
{
    int bn0 = blockIdx.x * 128, t0 = blockIdx.y * 128, z = blockIdx.z;
    if (bn0 + 383 <= t0) return;
    int h = z >> 1, b = z & 1;
    const bf16* A = g_qkvh + (size_t)b * TT * 3072 + h * 64;
    const bf16* B = g_krh + (size_t)z * 65536 + bn0;
    float acc[2][8][4] = {};
    hgemm_core2<128>(A, 3072, nullptr, t0, B, 1024, 64, acc);
    int lane = threadIdx.x & 31, warp = threadIdx.x >> 5;
    int wm = (warp >> 1) * 32, wn = (warp & 1) * 64;
    int gq = lane >> 2, tig = lane & 3;
    #pragma unroll
    for (int f = 0; f < 2; f++) {
        int r = t0 + wm + f * 16 + gq;
        #pragma unroll
        for (int j = 0; j < 8; j++) {
            int c = bn0 + wn + j * 8 + tig * 2;
            *(__nv_bfloat162*)&g_sch[(size_t)(z * TT + r) * TT + c] =
                __floats2bfloat162_rn(acc[f][j][0] * 0.125f, acc[f][j][1] * 0.125f);
            *(__nv_bfloat162*)&g_sch[(size_t)(z * TT + r + 8) * TT + c] =
                __floats2bfloat162_rn(acc[f][j][2] * 0.125f, acc[f][j][3] * 0.125f);
        }
    }
}

// ---------------- softmax (bf16 in/out, fp32 stats), contiguous x4 per thread ----------------
__global__ void __launch_bounds__(256) k_softmax()
{
    int t = blockIdx.x, z = blockIdx.y;
    const bf16* row = g_sch + (size_t)(z * TT + t) * TT;
    bf16* rout = g_wh + (size_t)(z * TT + t) * TT;
    int bound = t - (WIN - 1); if (bound < 0) bound = 0;
    int tid = threadIdx.x;
    int base = tid * 4;
    uint2 raw = *(const uint2*)&row[base];
    __nv_bfloat162 p0 = *(__nv_bfloat162*)&raw.x;
    __nv_bfloat162 p1 = *(__nv_bfloat162*)&raw.y;
    float v[4] = { __bfloat162float(p0.x), __bfloat162float(p0.y),
                   __bfloat162float(p1.x), __bfloat162float(p1.y) };
    float mx = -1e30f;
    #pragma unroll
    for (int i = 0; i < 4; i++) {
        if (base + i < bound) v[i] = -1e30f;
        mx = fmaxf(mx, v[i]);
    }
    __shared__ float red[256];
    red[tid] = mx; __syncthreads();
    for (int o = 128; o > 0; o >>= 1) { if (tid < o) red[tid] = fmaxf(red[tid], red[tid+o]); __syncthreads(); }
    mx = red[0]; __syncthreads();
    float sum = 0.f;
    #pragma unroll
    for (int i = 0; i < 4; i++) {
        v[i] = (base + i >= bound) ? expf(v[i] - mx) : 0.f;
        sum += v[i];
    }
    red[tid] = sum; __syncthreads();
    for (int o = 128; o > 0; o >>= 1) { if (tid < o) red[tid] += red[tid+o]; __syncthreads(); }
    float inv = 1.f / red[0];
    __nv_bfloat162 q0 = __floats2bfloat162_rn(v[0] * inv, v[1] * inv);
    __nv_bfloat162 q1 = __floats2bfloat162_rn(v[2] * inv, v[3] * inv);
    uint2 outw; outw.x = *(uint32_t*)&q0; outw.y = *(uint32_t*)&q1;
    *(uint2*)&rout[base] = outw;
}

// ---------------- o = w @ v (leading all-zero K range skipped; bitwise identical) ----------------
__global__ void __launch_bounds__(256) k_hgemm_o()
{
    int t0 = blockIdx.y * 128, z = blockIdx.z;
    int h = z >> 1, b = z & 1;
    int kstart = t0 - 255; if (kstart < 0) kstart = 0;
    kstart &= ~31;
    const bf16* A = g_wh + (size_t)z * TT * TT + kstart;
    const bf16* B = g_qkvh + (size_t)(b * TT + kstart) * 3072 + 2048 + h * 64;
    float acc[2][4][4] = {};
    hgemm_core2<64>(A, TT, nullptr, t0, B, 3072, TT - kstart, acc);
    int lane = threadIdx.x & 31, warp = threadIdx.x >> 5;
    int wm = (warp >> 1) * 32, wn = (warp & 1) * 32;
    int gq = lane >> 2, tig = lane & 3;
    #pragma unroll
    for (int f = 0; f < 2; f++) {
        int r = b * TT + t0 + wm + f * 16 + gq;
        #pragma unroll
        for (int j = 0; j < 4; j++) {
            int c = h * 64 + wn + j * 8 + tig * 2;
            *(__nv_bfloat162*)&g_oh[(size_t)r * CDIM + c] =
                __floats2bfloat162_rn(acc[f][j][0], acc[f][j][1]);
            *(__nv_bfloat162*)&g_oh[(size_t)(r + 8) * CDIM + c] =
                __floats2bfloat162_rn(acc[f][j][2], acc[f][j][3]);
        }
    }
}

// ---------------- x1 = x + o @ Wp + bp -> d_out ----------------
__global__ void __launch_bounds__(256) k_hgemm_wp(const float* __restrict__ x,
                                                  const float* __restrict__ bp,
                                                  float* __restrict__ dout)
{
    int bm0 = blockIdx.y * 128, bn0 = blockIdx.x * 128;
    float acc[2][8][4] = {};
    hgemm_core2<128>(g_oh, CDIM, nullptr, bm0, g_wph + bn0, CDIM, CDIM, acc);
    int lane = threadIdx.x & 31, warp = threadIdx.x >> 5;
    int wm = (warp >> 1) * 32, wn = (warp & 1) * 64;
    int gq = lane >> 2, tig = lane & 3;
    #pragma unroll
    for (int f = 0; f < 2; f++) {
        int r = bm0 + wm + f * 16 + gq;
        #pragma unroll
        for (int j = 0; j < 8; j++) {
            int c = bn0 + wn + j * 8 + tig * 2;
            size_t o0 = (size_t)r * CDIM + c;
            size_t o1 = (size_t)(r + 8) * CDIM + c;
            dout[o0]     = x[o0]     + acc[f][j][0] + bp[c];
            dout[o0 + 1] = x[o0 + 1] + acc[f][j][1] + bp[c + 1];
            dout[o1]     = x[o1]     + acc[f][j][2] + bp[c];
            dout[o1 + 1] = x[o1 + 1] + acc[f][j][3] + bp[c + 1];
        }
    }
}

// ---------------- router / coef / assign ----------------
__global__ void __launch_bounds__(256) k_router(const float* __restrict__ Wg,
                                                const float* __restrict__ bg)
{
    int t = blockIdx.x;
    const float* xr = g_xn2 + (size_t)t * CDIM;
    int tid = threadIdx.x;
    float l0 = 0.f, l1 = 0.f;
    for (int c = tid; c < CDIM; c += 256) {
        float xv = xr[c];
        l0 += xv * Wg[c * 2 + 0];
        l1 += xv * Wg[c * 2 + 1];
    }
    __shared__ float r0[256], r1[256];
    r0[tid] = l0; r1[tid] = l1; __syncthreads();
    for (int o = 128; o > 0; o >>= 1) {
        if (tid < o) { r0[tid] += r0[tid+o]; r1[tid] += r1[tid+o]; }
        __syncthreads();
    }
    if (tid == 0) {
        float a = r0[0] + bg[0], b = r1[0] + bg[1];
        int e = (a >= b) ? 0 : 1;
        g_eidx[t] = e;
        g_m[t] = fmaxf(a, b);
    }
}

// coef softmax over token dim per batch; also zeroes g_cnt
__global__ void __launch_bounds__(256) k_coef()
{
    int b = blockIdx.x, tid = threadIdx.x;
    if (tid == 0) g_cnt[b] = 0;
    __shared__ float red[256];
    float v[4]; float mx = -1e30f;
    #pragma unroll
    for (int i = 0; i < 4; i++) { v[i] = g_m[b * TT + tid + i*256]; mx = fmaxf(mx, v[i]); }
    red[tid] = mx; __syncthreads();
    for (int o = 128; o > 0; o >>= 1) { if (tid < o) red[tid] = fmaxf(red[tid], red[tid+o]); __syncthreads(); }
    mx = red[0]; __syncthreads();
    float sum = 0.f;
    #pragma unroll
    for (int i = 0; i < 4; i++) { v[i] = expf(v[i] - mx); sum += v[i]; }
    red[tid] = sum; __syncthreads();
    for (int o = 128; o > 0; o >>= 1) { if (tid < o) red[tid] += red[tid+o]; __syncthreads(); }
    float inv = 1.f / red[0];
    #pragma unroll
    for (int i = 0; i < 4; i++) g_coef[b * TT + tid + i*256] = v[i] * inv;
}

__global__ void k_assign()
{
    int t = blockIdx.x * blockDim.x + threadIdx.x;
    if (t >= TOK) return;
    int e = g_eidx[t];
    int pos = atomicAdd(&g_cnt[e], 1);
    int row = (e == 0) ? pos : (TOK - 1 - pos);
    g_perm[row] = t;
}

// ================= MoE GEMMs (bf16 weights) =================
__global__ void __launch_bounds__(256) k_hgemm_h1(const float* __restrict__ Eb1)
{
    int e = blockIdx.z, bm0 = blockIdx.y * 128, bn0 = blockIdx.x * 128;
    int cnt0 = g_cnt[0];
    if (e == 0 && bm0 >= cnt0) return;
    if (e == 1 && bm0 + 128 <= cnt0) return;
    float acc[2][8][4] = {};
    hgemm_core2<128>(g_xn2h, CDIM, g_perm, bm0, g_w1h + (size_t)e * CDIM * NHID + bn0, NHID, CDIM, acc);

    int lane = threadIdx.x & 31, warp = threadIdx.x >> 5;
    int wm = (warp >> 1) * 32, wn = (warp & 1) * 64;
    int gq = lane >> 2, tig = lane & 3;
    const float* bias = Eb1 + (size_t)e * NHID;
    #pragma unroll
    for (int f = 0; f < 2; f++) {
        int r = bm0 + wm + f * 16 + gq;
        bool v0 = (e == 0) ? (r < cnt0)     : (r >= cnt0);
        bool v1 = (e == 0) ? (r + 8 < cnt0) : (r + 8 >= cnt0);
        #pragma unroll
        for (int j = 0; j < 8; j++) {
            int c = bn0 + wn + j * 8 + tig * 2;
            float b0 = bias[c], b1 = bias[c + 1];
            if (v0) *(__nv_bfloat162*)&g_h1h[(size_t)r * NHID + c] =
                __floats2bfloat162_rn(acc[f][j][0] + b0, acc[f][j][1] + b1);
            if (v1) *(__nv_bfloat162*)&g_h1h[(size_t)(r + 8) * NHID + c] =
                __floats2bfloat162_rn(acc[f][j][2] + b0, acc[f][j][3] + b1);
        }
    }
}

// merged ff pair: z = e*2 + which; writes bf16 sx/glu
__global__ void __launch_bounds__(256) k_hgemm_ff(const float* __restrict__ Ebs,
                                                  const float* __restrict__ Ebg)
{
    int z = blockIdx.z;
    int e = z >> 1, which = z & 1;
    int bm0 = blockIdx.y * 128, bn0 = blockIdx.x * 128;
    int cnt0 = g_cnt[0];
    if (e == 0 && bm0 >= cnt0) return;
    if (e == 1 && bm0 + 128 <= cnt0) return;
    const bf16* W = (which ? g_wgh : g_wsh) + (size_t)e * NHID * NHID + bn0;
    const float* bias_all = which ? Ebg : Ebs;
    bf16* out = which ? g_gluh : g_sxh;
    float acc[2][8][4] = {};
    hgemm_core2<128>(g_h1h, NHID, nullptr, bm0, W, NHID, NHID, acc);

    int lane = threadIdx.x & 31, warp = threadIdx.x >> 5;
    int wm = (warp >> 1) * 32, wn = (warp & 1) * 64;
    int gq = lane >> 2, tig = lane & 3;
    const float* bias = bias_all + (size_t)e * NHID;
    #pragma unroll
    for (int f = 0; f < 2; f++) {
        int r = bm0 + wm + f * 16 + gq;
        bool v0 = (e == 0) ? (r < cnt0)     : (r >= cnt0);
        bool v1 = (e == 0) ? (r + 8 < cnt0) : (r + 8 >= cnt0);
        #pragma unroll
        for (int j = 0; j < 8; j++) {
            int c = bn0 + wn + j * 8 + tig * 2;
            float b0 = bias[c], b1 = bias[c + 1];
            if (v0) *(__nv_bfloat162*)&out[(size_t)r * NHID + c] =
                __floats2bfloat162_rn(acc[f][j][0] + b0, acc[f][j][1] + b1);
            if (v1) *(__nv_bfloat162*)&out[(size_t)(r + 8) * NHID + c] =
                __floats2bfloat162_rn(acc[f][j][2] + b0, acc[f][j][3] + b1);
        }
    }
}

// act = (sx * sigmoid(beta*sx)) * glu, bf16 in -> bf16 out, x4 vectorized
__global__ void k_act(const float* __restrict__ Ebeta)
{
    size_t i4 = (size_t)(blockIdx.x * blockDim.x + threadIdx.x) * 4;
    if (i4 >= (size_t)TOK * NHID) return;
    int row = (int)(i4 >> 12);
    int e = (row < g_cnt[0]) ? 0 : 1;
    float beta = Ebeta[e];
    uint2 sv = *(const uint2*)&g_sxh[i4];
    uint2 gv = *(const uint2*)&g_gluh[i4];
    __nv_bfloat162 s0 = *(__nv_bfloat162*)&sv.x, s1 = *(__nv_bfloat162*)&sv.y;
    __nv_bfloat162 g0 = *(__nv_bfloat162*)&gv.x, g1 = *(__nv_bfloat162*)&gv.y;
    float s[4] = { __bfloat162float(s0.x), __bfloat162float(s0.y),
                   __bfloat162float(s1.x), __bfloat162float(s1.y) };
    float g[4] = { __bfloat162float(g0.x), __bfloat162float(g0.y),
                   __bfloat162float(g1.x), __bfloat162float(g1.y) };
    float o[4];
    #pragma unroll
    for (int i = 0; i < 4; i++)
        o[i] = s[i] * (1.f / (1.f + expf(-beta * s[i]))) * g[i];
    __nv_bfloat162 q0 = __floats2bfloat162_rn(o[0], o[1]);
    __nv_bfloat162 q1 = __floats2bfloat162_rn(o[2], o[3]);
    uint2 outw; outw.x = *(uint32_t*)&q0; outw.y = *(uint32_t*)&q1;
    *(uint2*)&g_acth[i4] = outw;
}

__global__ void __launch_bounds__(256) k_hgemm_out(const float* __restrict__ Eb2,
                                                   float* __restrict__ dout)
{
    int e = blockIdx.z, bm0 = blockIdx.y * 128, bn0 = blockIdx.x * 128;
    int cnt0 = g_cnt[0];
    if (e == 0 && bm0 >= cnt0) return;
    if (e == 1 && bm0 + 128 <= cnt0) return;
    float acc[2][8][4] = {};
    hgemm_core2<128>(g_acth, NHID, nullptr, bm0, g_w2h + (size_t)e * NHID * CDIM + bn0, CDIM, NHID, acc);

    int lane = threadIdx.x & 31, warp = threadIdx.x >> 5;
    int wm = (warp >> 1) * 32, wn = (warp & 1) * 64;
    int gq = lane >> 2, tig = lane & 3;
    const float* bias = Eb2 + (size_t)e * CDIM;
    #pragma unroll
    for (int f = 0; f < 2; f++) {
        int r = bm0 + wm + f * 16 + gq;
        bool v0 = (e == 0) ? (r < cnt0)     : (r >= cnt0);
        bool v1 = (e == 0) ? (r + 8 < cnt0) : (r + 8 >= cnt0);
        int tok0 = v0 ? g_perm[r]     : 0;
        int tok1 = v1 ? g_perm[r + 8] : 0;
        float cf0 = v0 ? g_coef[tok0] : 0.f;
        float cf1 = v1 ? g_coef[tok1] : 0.f;
        #pragma unroll
        for (int j = 0; j < 8; j++) {
            int c = bn0 + wn + j * 8 + tig * 2;
            float b0 = bias[c], b1 = bias[c + 1];
            if (v0) {
                size_t o = (size_t)tok0 * CDIM + c;
                dout[o]     += cf0 * (acc[f][j][0] + b0);
                dout[o + 1] += cf0 * (acc[f][j][1] + b1);
            }
            if (v1) {
                size_t o = (size_t)tok1 * CDIM + c;
                dout[o]     += cf1 * (acc[f][j][2] + b0);
                dout[o + 1] += cf1 * (acc[f][j][3] + b1);
            }
        }
    }
}

// ---------------- launch ----------------
extern "C" void kernel_launch(void* const* d_in, const int* in_sizes, int n_in,
                              void* d_out, int out_size)
{
    const float* x     = (const float*)d_in[0];
    const float* Wq    = (const float*)d_in[1];
    const float* Wk    = (const float*)d_in[2];
    const float* Wv    = (const float*)d_in[3];
    const float* Wp    = (const float*)d_in[4];
    const float* bp    = (const float*)d_in[5];
    const float* ln1g  = (const float*)d_in[6];
    const float* ln1b  = (const float*)d_in[7];
    const float* ln2g  = (const float*)d_in[8];
    const float* ln2b  = (const float*)d_in[9];
    const float* Wg    = (const float*)d_in[10];
    const float* bg    = (const float*)d_in[11];
    const float* Ew1   = (const float*)d_in[12];
    const float* Eb1   = (const float*)d_in[13];
    const float* Ews   = (const float*)d_in[14];
    const float* Ebs   = (const float*)d_in[15];
    const float* Ebeta = (const float*)d_in[16];
    const float* Ewg   = (const float*)d_in[17];
    const float* Ebg   = (const float*)d_in[18];
    const float* Ew2   = (const float*)d_in[19];
    const float* Eb2   = (const float*)d_in[20];
    float* dout = (float*)d_out;

    // weight conversions (serial)
    k_convw<<<82944, 256>>>(Ew1, Ews, Ewg, Ew2, Wp);
    k_repack<<<(CDIM * 3072 + 255) / 256, 256>>>(Wq, Wk, Wv);

    // attention (mma.sync bf16)
    k_ln<<<TOK, 256>>>(x, ln1g, ln1b, 0);
    k_hgemm_qkv<<<dim3(24, 16), 256>>>();
    k_krep<<<2048, 256>>>();
    k_hgemm_scores<<<dim3(8, 8, 32), 256>>>();
    k_softmax<<<dim3(1024, 32), 256>>>();
    k_hgemm_o<<<dim3(1, 8, 32), 256>>>();
    k_hgemm_wp<<<dim3(8, 16), 256>>>(x, bp, dout);

    // MoE routing
    k_ln<<<TOK, 256>>>(dout, ln2g, ln2b, 1);
    k_router<<<TOK, 256>>>(Wg, bg);
    k_coef<<<2, 256>>>();
    k_assign<<<8, 256>>>();

    // MoE expert GEMMs (bf16 tensor cores)
    k_hgemm_h1<<<dim3(32, 16, 2), 256>>>(Eb1);
    k_hgemm_ff<<<dim3(32, 16, 4), 256>>>(Ebs, Ebg);
    k_act<<<(TOK * NHID / 4 + 255) / 256, 256>>>(Ebeta);
    k_hgemm_out<<<dim3(8, 16, 2), 256>>>(Eb2, dout);
}